// round 1
// baseline (speedup 1.0000x reference)
#include <cuda_runtime.h>

// Problem constants
#define BB   32
#define DD   256
#define HH   64
#define WW   64
#define CO   384   // 64 q + 256 v + 64 k
#define EPS  1e-5f

typedef unsigned long long u64;

__device__ __forceinline__ u64 pack2(float lo, float hi) {
    u64 r; asm("mov.b64 %0, {%1, %2};" : "=l"(r) : "f"(lo), "f"(hi)); return r;
}
__device__ __forceinline__ void unpack2(u64 v, float& lo, float& hi) {
    asm("mov.b64 {%0, %1}, %2;" : "=f"(lo), "=f"(hi) : "l"(v));
}
__device__ __forceinline__ void fma2(u64& d, u64 a, u64 b) {
    asm("fma.rn.f32x2 %0, %1, %2, %0;" : "+l"(d) : "l"(a), "l"(b));
}

// SMEM layout (floats):
//   sW : [384][65]  (o-major, pad 65 -> conflict-free scalar weight reads)
//   sX : [64][64]   (x tile: k-chunk rows x 64 pixels)
//   sC : [64][64]   (c tile)
#define SW_STRIDE 65
#define SW_ELEMS  (CO * SW_STRIDE)          // 24960
#define SX_ELEMS  (64 * 64)
#define SMEM_FLOATS (SW_ELEMS + 2 * SX_ELEMS)
#define SMEM_BYTES  (SMEM_FLOATS * 4)       // 132,608 B

__global__ __launch_bounds__(384, 1)
void lamba_kernel(const float* __restrict__ x,  const float* __restrict__ c,
                  const float* __restrict__ Wq, const float* __restrict__ Wv,
                  const float* __restrict__ Wk,
                  const float* __restrict__ qg, const float* __restrict__ qb,
                  const float* __restrict__ qm, const float* __restrict__ qv,
                  const float* __restrict__ vg, const float* __restrict__ vb,
                  const float* __restrict__ vm, const float* __restrict__ vv,
                  float* __restrict__ out)
{
    extern __shared__ float smem[];
    float* sW = smem;
    float* sX = smem + SW_ELEMS;
    float* sC = sX + SX_ELEMS;

    const int tid = threadIdx.x;        // 0..383
    const int tn  = tid & 7;            // pixel tile 0..7
    const int tm  = tid >> 3;           // channel tile 0..47
    const int bh  = blockIdx.x;         // 0..2047
    const int b   = bh >> 6;
    const int h   = bh & 63;
    const int w0  = tn * 8;
    const int oc0 = tm * 8;

    // 8 channels x 4 pixel-pairs of packed f32x2 accumulators
    u64 acc[8][4];
    #pragma unroll
    for (int i = 0; i < 8; i++)
        #pragma unroll
        for (int p = 0; p < 4; p++) acc[i][p] = 0ULL;

    const float* src = (oc0 < 64) ? sX : sC;   // q reduces over x; v,k over c
    const int gbase = b * (DD * HH * WW) + h * WW;   // d=0 element for this (b,h)

    for (int kc = 0; kc < DD; kc += 64) {
        __syncthreads();
        // --- stage x and c tiles: 64 rows x 64 pixels each, float4 coalesced ---
        #pragma unroll
        for (int r = 0; r < 3; r++) {
            int idx = tid + r * 384;
            if (idx < 1024) {                 // 1024 float4 per tile
                int kk = idx >> 4;
                int w4 = (idx & 15) << 2;
                int g  = gbase + (kc + kk) * (HH * WW) + w4;
                *(float4*)(sX + kk * 64 + w4) = *(const float4*)(x + g);
                *(float4*)(sC + kk * 64 + w4) = *(const float4*)(c + g);
            }
        }
        // --- stage weight chunk: all 384 out-channels x 64 k, o-major ---
        #pragma unroll
        for (int r = 0; r < 16; r++) {
            int idx = tid + r * 384;          // 0..6143, exactly 6144 float4
            int o   = idx >> 4;
            int k4  = (idx & 15) << 2;
            const float* Ws; int orow;
            if (o < 64)       { Ws = Wq; orow = o; }
            else if (o < 320) { Ws = Wv; orow = o - 64; }
            else              { Ws = Wk; orow = o - 320; }
            float4 wv4 = *(const float4*)(Ws + orow * DD + kc + k4);
            sW[o * SW_STRIDE + k4 + 0] = wv4.x;
            sW[o * SW_STRIDE + k4 + 1] = wv4.y;
            sW[o * SW_STRIDE + k4 + 2] = wv4.z;
            sW[o * SW_STRIDE + k4 + 3] = wv4.w;
        }
        __syncthreads();

        // --- compute: 8ch x 8px register tile, packed f32x2 FMAs ---
        #pragma unroll 4
        for (int kk = 0; kk < 64; kk++) {
            const float* xrow = src + kk * 64 + w0;
            ulonglong2 pa = *(const ulonglong2*)(xrow);
            ulonglong2 pb = *(const ulonglong2*)(xrow + 4);
            u64 px[4] = {pa.x, pa.y, pb.x, pb.y};
            u64 wp[8];
            #pragma unroll
            for (int i = 0; i < 8; i++) {
                float w = sW[(oc0 + i) * SW_STRIDE + kk];
                wp[i] = pack2(w, w);
            }
            #pragma unroll
            for (int i = 0; i < 8; i++)
                #pragma unroll
                for (int p = 0; p < 4; p++)
                    fma2(acc[i][p], px[p], wp[i]);
        }
    }

    // --- unpack accumulators ---
    float v[8][8];
    #pragma unroll
    for (int i = 0; i < 8; i++)
        #pragma unroll
        for (int p = 0; p < 4; p++)
            unpack2(acc[i][p], v[i][2 * p], v[i][2 * p + 1]);

    const int obase = ((b * CO + oc0) * HH + h) * WW + w0;

    if (oc0 < 320) {
        // ---- q / v channels: eval-mode BatchNorm, warp-uniform branch ----
        #pragma unroll
        for (int i = 0; i < 8; i++) {
            int o = oc0 + i;
            float g, be, mn, va;
            if (o < 64) { g = qg[o];     be = qb[o];     mn = qm[o];     va = qv[o]; }
            else        { g = vg[o-64];  be = vb[o-64];  mn = vm[o-64];  va = vv[o-64]; }
            float sc = g * rsqrtf(va + EPS);
            float sh = be - mn * sc;
            float4 o0 = make_float4(v[i][0]*sc+sh, v[i][1]*sc+sh, v[i][2]*sc+sh, v[i][3]*sc+sh);
            float4 o1 = make_float4(v[i][4]*sc+sh, v[i][5]*sc+sh, v[i][6]*sc+sh, v[i][7]*sc+sh);
            *(float4*)(out + obase + i * (HH * WW))     = o0;
            *(float4*)(out + obase + i * (HH * WW) + 4) = o1;
        }
    } else {
        // ---- k channels: softmax over the 64-pixel W row ----
        // The 8 threads (tn=0..7) holding one channel row sit in one 8-lane
        // group of the warp; k-channel tiles occupy warps 10,11 entirely,
        // so the shuffles below are warp-uniform.
        #pragma unroll
        for (int i = 0; i < 8; i++) {
            float m = v[i][0];
            #pragma unroll
            for (int j = 1; j < 8; j++) m = fmaxf(m, v[i][j]);
            #pragma unroll
            for (int d = 1; d < 8; d <<= 1)
                m = fmaxf(m, __shfl_xor_sync(0xffffffffu, m, d));
            float e[8], s = 0.0f;
            #pragma unroll
            for (int j = 0; j < 8; j++) { e[j] = __expf(v[i][j] - m); s += e[j]; }
            #pragma unroll
            for (int d = 1; d < 8; d <<= 1)
                s += __shfl_xor_sync(0xffffffffu, s, d);
            float inv = __frcp_rn(s);
            float4 o0 = make_float4(e[0]*inv, e[1]*inv, e[2]*inv, e[3]*inv);
            float4 o1 = make_float4(e[4]*inv, e[5]*inv, e[6]*inv, e[7]*inv);
            *(float4*)(out + obase + i * (HH * WW))     = o0;
            *(float4*)(out + obase + i * (HH * WW) + 4) = o1;
        }
    }
}

extern "C" void kernel_launch(void* const* d_in, const int* in_sizes, int n_in,
                              void* d_out, int out_size)
{
    const float* x  = (const float*)d_in[0];
    const float* c  = (const float*)d_in[1];
    const float* Wq = (const float*)d_in[2];
    const float* Wv = (const float*)d_in[3];
    const float* Wk = (const float*)d_in[4];
    const float* qg = (const float*)d_in[5];
    const float* qb = (const float*)d_in[6];
    const float* qm = (const float*)d_in[7];
    const float* qv = (const float*)d_in[8];
    const float* vg = (const float*)d_in[9];
    const float* vb = (const float*)d_in[10];
    const float* vm = (const float*)d_in[11];
    const float* vv = (const float*)d_in[12];
    float* out = (float*)d_out;

    cudaFuncSetAttribute(lamba_kernel,
                         cudaFuncAttributeMaxDynamicSharedMemorySize, SMEM_BYTES);
    lamba_kernel<<<BB * HH, 384, SMEM_BYTES>>>(
        x, c, Wq, Wv, Wk, qg, qb, qm, qv, vg, vb, vm, vv, out);
}